// round 7
// baseline (speedup 1.0000x reference)
#include <cuda_runtime.h>
#include <cuda_bf16.h>
#include <cuda_fp16.h>
#include <cstdint>

#define NMAX 100000
#define DIM 128
#define NREL 8
#define AS 136   // padded smem row stride (bf16 elems); 272B rows -> conflict-free LDSM

// Scratch (static device globals; runtime allocation is forbidden)
__device__ __half g_Yh[(size_t)NMAX * NREL * DIM];    // per-relation transformed feats (fp16)
__device__ float g_h[(size_t)NMAX * DIM];             // layer-1 accumulate buffer
__device__ float g_inv[NMAX * NREL];                  // 1/max(cnt,1), also cnt
__device__ __nv_bfloat16 g_Ahi[(size_t)NMAX * DIM];   // split-precision activations
__device__ __nv_bfloat16 g_Alo[(size_t)NMAX * DIM];
__device__ __nv_bfloat16 g_Wth[2 * 9 * DIM * DIM];    // transposed [n][k] weights hi
__device__ __nv_bfloat16 g_Wtl[2 * 9 * DIM * DIM];    // lo

// ---------------------------------------------------------------------------
// cnt / inv
// ---------------------------------------------------------------------------
__global__ void zero_inv_kernel(int n8) {
    int i = blockIdx.x * blockDim.x + threadIdx.x;
    if (i < n8) g_inv[i] = 0.0f;
}

__global__ void count_kernel(const int* __restrict__ ei,
                             const int* __restrict__ et, int e) {
    int i = blockIdx.x * blockDim.x + threadIdx.x;
    if (i >= e) return;
    atomicAdd(&g_inv[ei[e + i] * NREL + et[i]], 1.0f);
}

__global__ void invert_kernel(int n8) {
    int i = blockIdx.x * blockDim.x + threadIdx.x;
    if (i < n8) g_inv[i] = 1.0f / fmaxf(g_inv[i], 1.0f);
}

// ---------------------------------------------------------------------------
// Split-precision conversions
// ---------------------------------------------------------------------------
__device__ __forceinline__ void split_bf16(float v, unsigned short& h, unsigned short& l) {
    __nv_bfloat16 bh = __float2bfloat16(v);
    float r = v - __bfloat162float(bh);
    __nv_bfloat16 bl = __float2bfloat16(r);
    h = *reinterpret_cast<unsigned short*>(&bh);
    l = *reinterpret_cast<unsigned short*>(&bl);
}

__global__ void convert_split_kernel(const float* __restrict__ src, int nelem4, int do_relu) {
    int i = blockIdx.x * blockDim.x + threadIdx.x;
    if (i >= nelem4) return;
    float4 v = ((const float4*)src)[i];
    if (do_relu) {
        v.x = fmaxf(v.x, 0.f); v.y = fmaxf(v.y, 0.f);
        v.z = fmaxf(v.z, 0.f); v.w = fmaxf(v.w, 0.f);
    }
    ushort4 hs, ls;
    split_bf16(v.x, hs.x, ls.x);
    split_bf16(v.y, hs.y, ls.y);
    split_bf16(v.z, hs.z, ls.z);
    split_bf16(v.w, hs.w, ls.w);
    ((ushort4*)g_Ahi)[i] = hs;
    ((ushort4*)g_Alo)[i] = ls;
}

// weights [k][n] fp32 -> transposed [bn][n][k] bf16 hi/lo
__global__ void wconvert_kernel(const float* __restrict__ root,
                                const float* __restrict__ rel,
                                __nv_bfloat16* __restrict__ wth,
                                __nv_bfloat16* __restrict__ wtl) {
    int i = blockIdx.x * blockDim.x + threadIdx.x;
    if (i >= 9 * DIM * DIM) return;
    int bn = i >> 14;
    int t  = i & 16383;
    int n  = t >> 7;
    int k  = t & 127;
    float w = bn ? rel[(size_t)(bn - 1) * DIM * DIM + k * DIM + n] : root[k * DIM + n];
    unsigned short h, l;
    split_bf16(w, h, l);
    wth[i] = *reinterpret_cast<__nv_bfloat16*>(&h);
    wtl[i] = *reinterpret_cast<__nv_bfloat16*>(&l);
}

// ---------------------------------------------------------------------------
// Tensor-core GEMM (mma m16n8k16 bf16, 3-product split), ldmatrix fragments.
//   Tile: M=128 x N=128 x K=128 one-shot. 256 threads = 8 warps (4 wm x 2 wn),
//   warp tile 32x64. blockIdx.x = bn (0 root->fp32+bias; 1..8 -> g_Yh fp16).
// ---------------------------------------------------------------------------
#define MMA16816(d, a, b)                                                  \
    asm volatile(                                                          \
        "mma.sync.aligned.m16n8k16.row.col.f32.bf16.bf16.f32 "             \
        "{%0,%1,%2,%3},{%4,%5,%6,%7},{%8,%9},{%0,%1,%2,%3};"               \
        : "+f"(d[0]), "+f"(d[1]), "+f"(d[2]), "+f"(d[3])                   \
        : "r"(a[0]), "r"(a[1]), "r"(a[2]), "r"(a[3]), "r"(b[0]), "r"(b[1]))

#define LDSM4(R, ADDR)                                                     \
    asm volatile("ldmatrix.sync.aligned.m8n8.x4.shared.b16 "               \
                 "{%0,%1,%2,%3}, [%4];"                                    \
                 : "=r"(R[0]), "=r"(R[1]), "=r"(R[2]), "=r"(R[3])          \
                 : "r"(ADDR))

__global__ __launch_bounds__(256) void gemm_mma_kernel(
    const __nv_bfloat16* __restrict__ wth,   // layer base [9][128][128] (n,k)
    const __nv_bfloat16* __restrict__ wtl,
    const float* __restrict__ bias,
    float* __restrict__ outroot, int nrows)
{
    extern __shared__ __nv_bfloat16 smem[];
    __nv_bfloat16* sAh = smem;                   // 128 x AS
    __nv_bfloat16* sAl = sAh + 128 * AS;
    __nv_bfloat16* sBh = sAl + 128 * AS;         // 128 x AS
    __nv_bfloat16* sBl = sBh + 128 * AS;

    const int bn   = blockIdx.x;
    const int row0 = blockIdx.y * 128;
    const int tid  = threadIdx.x;
    const int lane = tid & 31;
    const int warp = tid >> 5;
    const int wm   = warp & 3;    // M offset 32*wm
    const int wn   = warp >> 2;   // N offset 64*wn
    const int grp  = lane >> 2;
    const int tg   = lane & 3;

    // ---- stage A tiles (hi/lo), 16B chunks, zero-fill OOB rows ----
#pragma unroll
    for (int it = 0; it < 8; it++) {
        int id = tid + it * 256;
        int r  = id >> 4;          // 0..127
        int c  = id & 15;
        int gr = row0 + r;
        uint4 vh = make_uint4(0, 0, 0, 0), vl = make_uint4(0, 0, 0, 0);
        if (gr < nrows) {
            vh = *(const uint4*)(g_Ahi + (size_t)gr * DIM + c * 8);
            vl = *(const uint4*)(g_Alo + (size_t)gr * DIM + c * 8);
        }
        *(uint4*)(sAh + r * AS + c * 8) = vh;
        *(uint4*)(sAl + r * AS + c * 8) = vl;
    }
    // ---- stage B (weight matrix bn), [n][k] ----
    const __nv_bfloat16* Bh = wth + (size_t)bn * DIM * DIM;
    const __nv_bfloat16* Bl = wtl + (size_t)bn * DIM * DIM;
#pragma unroll
    for (int it = 0; it < 8; it++) {
        int id = tid + it * 256;
        int r  = id >> 4;
        int c  = id & 15;
        *(uint4*)(sBh + r * AS + c * 8) = *(const uint4*)(Bh + r * DIM + c * 8);
        *(uint4*)(sBl + r * AS + c * 8) = *(const uint4*)(Bl + r * DIM + c * 8);
    }
    __syncthreads();

    // ldmatrix lane addressing (byte offsets into smem window)
    const unsigned sAhB = (unsigned)__cvta_generic_to_shared(sAh);
    const unsigned sAlB = (unsigned)__cvta_generic_to_shared(sAl);
    const unsigned sBhB = (unsigned)__cvta_generic_to_shared(sBh);
    const unsigned sBlB = (unsigned)__cvta_generic_to_shared(sBl);
    // A: tiles (m0..m0+7,k0),(m0+8..,k0),(m0..,k0+8),(m0+8..,k0+8)
    const unsigned aoff = (unsigned)(((wm * 32 + (lane & 15)) * AS +
                                      ((lane >> 4) << 3)) * 2);
    // B: tiles (n0+p16..,k0),(...,k0+8),(n0+p16+8..,k0),(...,k0+8)
    const unsigned boff = (unsigned)(((wn * 64 + ((lane >> 4) << 3) + (lane & 7)) * AS +
                                      (((lane >> 3) & 1) << 3)) * 2);

    float acc[2][8][4];
#pragma unroll
    for (int mi = 0; mi < 2; mi++)
#pragma unroll
        for (int ni = 0; ni < 8; ni++)
#pragma unroll
            for (int q = 0; q < 4; q++) acc[mi][ni][q] = 0.0f;

#pragma unroll
    for (int ks = 0; ks < 8; ks++) {
        const unsigned kb = ks * 32;   // 16 elems * 2B
        unsigned ah[2][4], al[2][4];
#pragma unroll
        for (int mi = 0; mi < 2; mi++) {
            unsigned d = aoff + mi * (16 * AS * 2) + kb;
            LDSM4(ah[mi], sAhB + d);
            LDSM4(al[mi], sAlB + d);
        }
        unsigned bh[8][2], bl[8][2];
#pragma unroll
        for (int p = 0; p < 4; p++) {
            unsigned d = boff + p * (16 * AS * 2) + kb;
            unsigned th[4], tl[4];
            LDSM4(th, sBhB + d);
            LDSM4(tl, sBlB + d);
            bh[2 * p][0] = th[0]; bh[2 * p][1] = th[1];
            bh[2 * p + 1][0] = th[2]; bh[2 * p + 1][1] = th[3];
            bl[2 * p][0] = tl[0]; bl[2 * p][1] = tl[1];
            bl[2 * p + 1][0] = tl[2]; bl[2 * p + 1][1] = tl[3];
        }
#pragma unroll
        for (int ni = 0; ni < 8; ni++)
#pragma unroll
            for (int mi = 0; mi < 2; mi++) {
                MMA16816(acc[mi][ni], ah[mi], bh[ni]);
                MMA16816(acc[mi][ni], ah[mi], bl[ni]);
                MMA16816(acc[mi][ni], al[mi], bh[ni]);
            }
    }

    // ---- epilogue ----
#pragma unroll
    for (int mi = 0; mi < 2; mi++) {
        int r0 = row0 + wm * 32 + mi * 16 + grp;
#pragma unroll
        for (int ni = 0; ni < 8; ni++) {
            int col = wn * 64 + ni * 8 + 2 * tg;
            if (bn == 0) {
                float b0 = bias[col], b1 = bias[col + 1];
                if (r0 < nrows) {
                    float2 o = make_float2(acc[mi][ni][0] + b0, acc[mi][ni][1] + b1);
                    *(float2*)&outroot[(size_t)r0 * DIM + col] = o;
                }
                if (r0 + 8 < nrows) {
                    float2 o = make_float2(acc[mi][ni][2] + b0, acc[mi][ni][3] + b1);
                    *(float2*)&outroot[(size_t)(r0 + 8) * DIM + col] = o;
                }
            } else {
                int rel = bn - 1;
                if (r0 < nrows) {
                    __half2 o = __floats2half2_rn(acc[mi][ni][0], acc[mi][ni][1]);
                    *(__half2*)&g_Yh[((size_t)r0 * NREL + rel) * DIM + col] = o;
                }
                if (r0 + 8 < nrows) {
                    __half2 o = __floats2half2_rn(acc[mi][ni][2], acc[mi][ni][3]);
                    *(__half2*)&g_Yh[((size_t)(r0 + 8) * NREL + rel) * DIM + col] = o;
                }
            }
        }
    }
}

// ---------------------------------------------------------------------------
// Edge scatter: one warp per edge; out[dst] += Yh[src][r] * inv[dst][r]
// fp16 gather (8B/lane) -> fp32 vectorized reduction (16B/lane).
// ---------------------------------------------------------------------------
__global__ __launch_bounds__(256) void scatter_kernel(
    const int* __restrict__ ei, const int* __restrict__ et,
    float* __restrict__ out, int e)
{
    int g = blockIdx.x * blockDim.x + threadIdx.x;
    int warp = g >> 5;
    int lane = g & 31;
    if (warp >= e) return;
    int src = ei[warp];
    int dst = ei[e + warp];
    int r   = et[warp];
    float s = g_inv[dst * NREL + r];
    const uint2 v =
        *(const uint2*)(g_Yh + (((size_t)src * NREL + r) << 7) + (lane << 2));
    float2 f0 = __half22float2(*reinterpret_cast<const __half2*>(&v.x));
    float2 f1 = __half22float2(*reinterpret_cast<const __half2*>(&v.y));
    float* p = out + (size_t)dst * DIM + (lane << 2);
    asm volatile("red.global.add.v4.f32 [%0], {%1,%2,%3,%4};"
                 :: "l"(p), "f"(f0.x * s), "f"(f0.y * s), "f"(f1.x * s), "f"(f1.y * s)
                 : "memory");
}

__global__ void relu_kernel(float* __restrict__ p, int n) {
    int i = blockIdx.x * blockDim.x + threadIdx.x;
    if (i < n) p[i] = fmaxf(p[i], 0.0f);
}

// ---------------------------------------------------------------------------
// Launch
// ---------------------------------------------------------------------------
extern "C" void kernel_launch(void* const* d_in, const int* in_sizes, int n_in,
                              void* d_out, int out_size)
{
    const float* x   = (const float*)d_in[0];
    const int*   ei  = (const int*)d_in[1];  // [2,E] int32
    const int*   et  = (const int*)d_in[2];  // [E]   int32
    const float* rw1 = (const float*)d_in[3];
    const float* ro1 = (const float*)d_in[4];
    const float* b1  = (const float*)d_in[5];
    const float* rw2 = (const float*)d_in[6];
    const float* ro2 = (const float*)d_in[7];
    const float* b2  = (const float*)d_in[8];
    float* out = (float*)d_out;

    const int n = in_sizes[0] / DIM;
    const int e = in_sizes[2];

    float* hptr;
    cudaGetSymbolAddress((void**)&hptr, g_h);
    __nv_bfloat16 *wth, *wtl;
    cudaGetSymbolAddress((void**)&wth, g_Wth);
    cudaGetSymbolAddress((void**)&wtl, g_Wtl);

    const int smem_bytes = 4 * 128 * AS * 2;   // 139264
    static bool attr_done = false;
    if (!attr_done) {
        cudaFuncSetAttribute(gemm_mma_kernel,
                             cudaFuncAttributeMaxDynamicSharedMemorySize, smem_bytes);
        attr_done = true;
    }

    const int n8 = n * NREL;
    dim3 ggrid(NREL + 1, (n + 127) / 128);
    const int scat_blocks = (e * 32 + 255) / 256;
    const int nw = 9 * DIM * DIM;

    // shared edge statistics (same graph both layers)
    zero_inv_kernel<<<(n8 + 255) / 256, 256>>>(n8);
    count_kernel<<<(e + 255) / 256, 256>>>(ei, et, e);
    invert_kernel<<<(n8 + 255) / 256, 256>>>(n8);

    // weight + activation split conversion
    wconvert_kernel<<<(nw + 255) / 256, 256>>>(ro1, rw1, wth, wtl);
    wconvert_kernel<<<(nw + 255) / 256, 256>>>(ro2, rw2, wth + nw, wtl + nw);
    convert_split_kernel<<<(n * 32 + 255) / 256, 256>>>(x, n * 32, 0);

    // layer 1
    gemm_mma_kernel<<<ggrid, 256, smem_bytes>>>(wth, wtl, b1, hptr, n);
    scatter_kernel<<<scat_blocks, 256>>>(ei, et, hptr, e);
    convert_split_kernel<<<(n * 32 + 255) / 256, 256>>>(hptr, n * 32, 1);  // relu fused

    // layer 2
    gemm_mma_kernel<<<ggrid, 256, smem_bytes>>>(wth + nw, wtl + nw, b2, out, n);
    scatter_kernel<<<scat_blocks, 256>>>(ei, et, out, e);
    relu_kernel<<<(n * DIM + 255) / 256, 256>>>(out, n * DIM);
}

// round 8
// speedup vs baseline: 1.6445x; 1.6445x over previous
#include <cuda_runtime.h>
#include <cuda_bf16.h>
#include <cuda_fp16.h>
#include <cstdint>

#define NMAX 100000
#define DIM 128
#define NREL 8
#define AS 136   // padded smem row stride (halfs); 272B rows -> conflict-free LDSM

// Scratch (static device globals; runtime allocation is forbidden)
__device__ __half g_Yh[(size_t)NMAX * NREL * DIM];    // per-relation transformed feats (fp16)
__device__ float g_h[(size_t)NMAX * DIM];             // layer-1 accumulate buffer
__device__ float g_inv[NMAX * NREL];                  // 1/max(cnt,1), also cnt
__device__ __half g_Af[(size_t)NMAX * DIM];           // fp16 activations
__device__ __half g_Wf[2 * 9 * DIM * DIM];            // fp16 transposed [bn][n][k] weights

// ---------------------------------------------------------------------------
// cnt / inv
// ---------------------------------------------------------------------------
__global__ void zero_inv_kernel(int n8) {
    int i = blockIdx.x * blockDim.x + threadIdx.x;
    if (i < n8) g_inv[i] = 0.0f;
}

__global__ void count_kernel(const int* __restrict__ ei,
                             const int* __restrict__ et, int e) {
    int i = blockIdx.x * blockDim.x + threadIdx.x;
    if (i >= e) return;
    atomicAdd(&g_inv[ei[e + i] * NREL + et[i]], 1.0f);
}

__global__ void invert_kernel(int n8) {
    int i = blockIdx.x * blockDim.x + threadIdx.x;
    if (i < n8) g_inv[i] = 1.0f / fmaxf(g_inv[i], 1.0f);
}

// ---------------------------------------------------------------------------
// fp16 conversions
// ---------------------------------------------------------------------------
// src fp32 -> g_Af fp16, optional fused relu. nelem4 = n*DIM/4
__global__ void convert_half_kernel(const float* __restrict__ src, int nelem4, int do_relu) {
    int i = blockIdx.x * blockDim.x + threadIdx.x;
    if (i >= nelem4) return;
    float4 v = ((const float4*)src)[i];
    if (do_relu) {
        v.x = fmaxf(v.x, 0.f); v.y = fmaxf(v.y, 0.f);
        v.z = fmaxf(v.z, 0.f); v.w = fmaxf(v.w, 0.f);
    }
    __half2 h0 = __floats2half2_rn(v.x, v.y);
    __half2 h1 = __floats2half2_rn(v.z, v.w);
    uint2 packed = make_uint2(*reinterpret_cast<unsigned*>(&h0),
                              *reinterpret_cast<unsigned*>(&h1));
    ((uint2*)g_Af)[i] = packed;
}

// weights [k][n] fp32 -> transposed [bn][n][k] fp16
__global__ void wconvert_kernel(const float* __restrict__ root,
                                const float* __restrict__ rel,
                                __half* __restrict__ wf) {
    int i = blockIdx.x * blockDim.x + threadIdx.x;
    if (i >= 9 * DIM * DIM) return;
    int bn = i >> 14;
    int t  = i & 16383;
    int n  = t >> 7;
    int k  = t & 127;
    float w = bn ? rel[(size_t)(bn - 1) * DIM * DIM + k * DIM + n] : root[k * DIM + n];
    wf[i] = __float2half_rn(w);
}

// ---------------------------------------------------------------------------
// Tensor-core GEMM (mma m16n8k16 fp16, single pass, fp32 accum), ldmatrix.
//   Tile: M=128 x N=128 x K=128 one-shot. 256 threads = 8 warps (4 wm x 2 wn),
//   warp tile 32x64. blockIdx.x = bn (0 root->fp32+bias; 1..8 -> g_Yh fp16).
// ---------------------------------------------------------------------------
#define MMA16816(d, a, b)                                                  \
    asm volatile(                                                          \
        "mma.sync.aligned.m16n8k16.row.col.f32.f16.f16.f32 "               \
        "{%0,%1,%2,%3},{%4,%5,%6,%7},{%8,%9},{%0,%1,%2,%3};"               \
        : "+f"(d[0]), "+f"(d[1]), "+f"(d[2]), "+f"(d[3])                   \
        : "r"(a[0]), "r"(a[1]), "r"(a[2]), "r"(a[3]), "r"(b[0]), "r"(b[1]))

#define LDSM4(R, ADDR)                                                     \
    asm volatile("ldmatrix.sync.aligned.m8n8.x4.shared.b16 "               \
                 "{%0,%1,%2,%3}, [%4];"                                    \
                 : "=r"(R[0]), "=r"(R[1]), "=r"(R[2]), "=r"(R[3])          \
                 : "r"(ADDR))

__global__ __launch_bounds__(256) void gemm_mma_kernel(
    const __half* __restrict__ wf,   // layer base [9][128][128] (n,k)
    const float* __restrict__ bias,
    float* __restrict__ outroot, int nrows)
{
    extern __shared__ __half smem[];
    __half* sA = smem;                 // 128 x AS
    __half* sB = sA + 128 * AS;        // 128 x AS

    const int bn   = blockIdx.x;
    const int row0 = blockIdx.y * 128;
    const int tid  = threadIdx.x;
    const int lane = tid & 31;
    const int warp = tid >> 5;
    const int wm   = warp & 3;    // M offset 32*wm
    const int wn   = warp >> 2;   // N offset 64*wn
    const int grp  = lane >> 2;
    const int tg   = lane & 3;

    // ---- stage A tile, 16B chunks, zero-fill OOB rows ----
#pragma unroll
    for (int it = 0; it < 8; it++) {
        int id = tid + it * 256;
        int r  = id >> 4;          // 0..127
        int c  = id & 15;
        int gr = row0 + r;
        uint4 v = make_uint4(0, 0, 0, 0);
        if (gr < nrows)
            v = *(const uint4*)(g_Af + (size_t)gr * DIM + c * 8);
        *(uint4*)(sA + r * AS + c * 8) = v;
    }
    // ---- stage B (weight matrix bn), [n][k] ----
    const __half* B = wf + (size_t)bn * DIM * DIM;
#pragma unroll
    for (int it = 0; it < 8; it++) {
        int id = tid + it * 256;
        int r  = id >> 4;
        int c  = id & 15;
        *(uint4*)(sB + r * AS + c * 8) = *(const uint4*)(B + r * DIM + c * 8);
    }
    __syncthreads();

    // ldmatrix lane addressing (byte offsets into smem window)
    const unsigned sAB = (unsigned)__cvta_generic_to_shared(sA);
    const unsigned sBB = (unsigned)__cvta_generic_to_shared(sB);
    // A: tiles (m0..m0+7,k0),(m0+8..,k0),(m0..,k0+8),(m0+8..,k0+8)
    const unsigned aoff = (unsigned)(((wm * 32 + (lane & 15)) * AS +
                                      ((lane >> 4) << 3)) * 2);
    // B: tiles (n0+p16..,k0),(...,k0+8),(n0+p16+8..,k0),(...,k0+8)
    const unsigned boff = (unsigned)(((wn * 64 + ((lane >> 4) << 3) + (lane & 7)) * AS +
                                      (((lane >> 3) & 1) << 3)) * 2);

    float acc[2][8][4];
#pragma unroll
    for (int mi = 0; mi < 2; mi++)
#pragma unroll
        for (int ni = 0; ni < 8; ni++)
#pragma unroll
            for (int q = 0; q < 4; q++) acc[mi][ni][q] = 0.0f;

#pragma unroll
    for (int ks = 0; ks < 8; ks++) {
        const unsigned kb = ks * 32;   // 16 elems * 2B
        unsigned a[2][4];
#pragma unroll
        for (int mi = 0; mi < 2; mi++)
            LDSM4(a[mi], sAB + aoff + mi * (16 * AS * 2) + kb);
        unsigned b[8][2];
#pragma unroll
        for (int p = 0; p < 4; p++) {
            unsigned t[4];
            LDSM4(t, sBB + boff + p * (16 * AS * 2) + kb);
            b[2 * p][0] = t[0]; b[2 * p][1] = t[1];
            b[2 * p + 1][0] = t[2]; b[2 * p + 1][1] = t[3];
        }
#pragma unroll
        for (int ni = 0; ni < 8; ni++)
#pragma unroll
            for (int mi = 0; mi < 2; mi++)
                MMA16816(acc[mi][ni], a[mi], b[ni]);
    }

    // ---- epilogue ----
#pragma unroll
    for (int mi = 0; mi < 2; mi++) {
        int r0 = row0 + wm * 32 + mi * 16 + grp;
#pragma unroll
        for (int ni = 0; ni < 8; ni++) {
            int col = wn * 64 + ni * 8 + 2 * tg;
            if (bn == 0) {
                float b0 = bias[col], b1 = bias[col + 1];
                if (r0 < nrows) {
                    float2 o = make_float2(acc[mi][ni][0] + b0, acc[mi][ni][1] + b1);
                    *(float2*)&outroot[(size_t)r0 * DIM + col] = o;
                }
                if (r0 + 8 < nrows) {
                    float2 o = make_float2(acc[mi][ni][2] + b0, acc[mi][ni][3] + b1);
                    *(float2*)&outroot[(size_t)(r0 + 8) * DIM + col] = o;
                }
            } else {
                int rel = bn - 1;
                if (r0 < nrows) {
                    __half2 o = __floats2half2_rn(acc[mi][ni][0], acc[mi][ni][1]);
                    *(__half2*)&g_Yh[((size_t)r0 * NREL + rel) * DIM + col] = o;
                }
                if (r0 + 8 < nrows) {
                    __half2 o = __floats2half2_rn(acc[mi][ni][2], acc[mi][ni][3]);
                    *(__half2*)&g_Yh[((size_t)(r0 + 8) * NREL + rel) * DIM + col] = o;
                }
            }
        }
    }
}

// ---------------------------------------------------------------------------
// Edge scatter: one warp per edge; out[dst] += Yh[src][r] * inv[dst][r]
// fp16 gather (8B/lane) -> fp32 vectorized reduction (16B/lane).
// ---------------------------------------------------------------------------
__global__ __launch_bounds__(256) void scatter_kernel(
    const int* __restrict__ ei, const int* __restrict__ et,
    float* __restrict__ out, int e)
{
    int g = blockIdx.x * blockDim.x + threadIdx.x;
    int warp = g >> 5;
    int lane = g & 31;
    if (warp >= e) return;
    int src = ei[warp];
    int dst = ei[e + warp];
    int r   = et[warp];
    float s = g_inv[dst * NREL + r];
    const uint2 v =
        *(const uint2*)(g_Yh + (((size_t)src * NREL + r) << 7) + (lane << 2));
    float2 f0 = __half22float2(*reinterpret_cast<const __half2*>(&v.x));
    float2 f1 = __half22float2(*reinterpret_cast<const __half2*>(&v.y));
    float* p = out + (size_t)dst * DIM + (lane << 2);
    asm volatile("red.global.add.v4.f32 [%0], {%1,%2,%3,%4};"
                 :: "l"(p), "f"(f0.x * s), "f"(f0.y * s), "f"(f1.x * s), "f"(f1.y * s)
                 : "memory");
}

__global__ void relu_kernel(float* __restrict__ p, int n) {
    int i = blockIdx.x * blockDim.x + threadIdx.x;
    if (i < n) p[i] = fmaxf(p[i], 0.0f);
}

// ---------------------------------------------------------------------------
// Launch  (order arranged so gemm_mma_kernel is launch index 5 for ncu -s 5)
// ---------------------------------------------------------------------------
extern "C" void kernel_launch(void* const* d_in, const int* in_sizes, int n_in,
                              void* d_out, int out_size)
{
    const float* x   = (const float*)d_in[0];
    const int*   ei  = (const int*)d_in[1];  // [2,E] int32
    const int*   et  = (const int*)d_in[2];  // [E]   int32
    const float* rw1 = (const float*)d_in[3];
    const float* ro1 = (const float*)d_in[4];
    const float* b1  = (const float*)d_in[5];
    const float* rw2 = (const float*)d_in[6];
    const float* ro2 = (const float*)d_in[7];
    const float* b2  = (const float*)d_in[8];
    float* out = (float*)d_out;

    const int n = in_sizes[0] / DIM;
    const int e = in_sizes[2];

    float* hptr;
    cudaGetSymbolAddress((void**)&hptr, g_h);
    __half* wf;
    cudaGetSymbolAddress((void**)&wf, g_Wf);

    const int smem_bytes = 2 * 128 * AS * 2;   // 69632
    static bool attr_done = false;
    if (!attr_done) {
        cudaFuncSetAttribute(gemm_mma_kernel,
                             cudaFuncAttributeMaxDynamicSharedMemorySize, smem_bytes);
        attr_done = true;
    }

    const int n8 = n * NREL;
    dim3 ggrid(NREL + 1, (n + 127) / 128);
    const int scat_blocks = (e * 32 + 255) / 256;
    const int nw = 9 * DIM * DIM;

    // idx 0-2: conversions first (also warms L2 for gemm)
    wconvert_kernel<<<(nw + 255) / 256, 256>>>(ro1, rw1, wf);
    wconvert_kernel<<<(nw + 255) / 256, 256>>>(ro2, rw2, wf + nw);
    convert_half_kernel<<<(n * 32 + 255) / 256, 256>>>(x, n * 32, 0);

    // idx 3-4: edge stats (shared by both layers)
    zero_inv_kernel<<<(n8 + 255) / 256, 256>>>(n8);
    count_kernel<<<(e + 255) / 256, 256>>>(ei, et, e);

    // idx 5: layer-1 GEMM  (profiled launch under ncu -s 5 -c 1)
    gemm_mma_kernel<<<ggrid, 256, smem_bytes>>>(wf, b1, hptr, n);

    // idx 6: finish edge stats before scatter
    invert_kernel<<<(n8 + 255) / 256, 256>>>(n8);

    // layer 1 rest
    scatter_kernel<<<scat_blocks, 256>>>(ei, et, hptr, e);
    convert_half_kernel<<<(n * 32 + 255) / 256, 256>>>(hptr, n * 32, 1);  // relu fused

    // layer 2
    gemm_mma_kernel<<<ggrid, 256, smem_bytes>>>(wf + nw, b2, out, n);
    scatter_kernel<<<scat_blocks, 256>>>(ei, et, out, e);
    relu_kernel<<<(n * DIM + 255) / 256, 256>>>(out, n * DIM);
}

// round 9
// speedup vs baseline: 1.6453x; 1.0005x over previous
#include <cuda_runtime.h>
#include <cuda_bf16.h>
#include <cuda_fp16.h>
#include <cstdint>

#define NMAX 100000
#define DIM 128
#define NREL 8
#define AS 136   // padded smem row stride (halfs); 272B rows -> conflict-free LDSM

// Scratch (static device globals; runtime allocation is forbidden)
__device__ __half g_Yh[(size_t)NMAX * NREL * DIM];    // per-relation transformed feats (fp16)
__device__ float g_h[(size_t)NMAX * DIM];             // layer-1 accumulate buffer
__device__ __half g_Af[(size_t)NMAX * DIM];           // fp16 activations
__device__ __half g_Wf[2 * 9 * DIM * DIM];            // fp16 transposed [bn][n][k] weights
// CSR sort structures (shared by both layers)
__device__ int g_cnt[NMAX * NREL];
__device__ int g_off[NMAX * NREL + 1];
__device__ int g_cursor[NMAX * NREL];
__device__ int g_bsum[1024];
__device__ int g_esrc[640000];

// ---------------------------------------------------------------------------
// fp16 conversions
// ---------------------------------------------------------------------------
__global__ void convert_half_kernel(const float* __restrict__ src, int nelem4, int do_relu) {
    int i = blockIdx.x * blockDim.x + threadIdx.x;
    if (i >= nelem4) return;
    float4 v = ((const float4*)src)[i];
    if (do_relu) {
        v.x = fmaxf(v.x, 0.f); v.y = fmaxf(v.y, 0.f);
        v.z = fmaxf(v.z, 0.f); v.w = fmaxf(v.w, 0.f);
    }
    __half2 h0 = __floats2half2_rn(v.x, v.y);
    __half2 h1 = __floats2half2_rn(v.z, v.w);
    uint2 packed = make_uint2(*reinterpret_cast<unsigned*>(&h0),
                              *reinterpret_cast<unsigned*>(&h1));
    ((uint2*)g_Af)[i] = packed;
}

// weights [k][n] fp32 -> transposed [bn][n][k] fp16
__global__ void wconvert_kernel(const float* __restrict__ root,
                                const float* __restrict__ rel,
                                __half* __restrict__ wf) {
    int i = blockIdx.x * blockDim.x + threadIdx.x;
    if (i >= 9 * DIM * DIM) return;
    int bn = i >> 14;
    int t  = i & 16383;
    int n  = t >> 7;
    int k  = t & 127;
    float w = bn ? rel[(size_t)(bn - 1) * DIM * DIM + k * DIM + n] : root[k * DIM + n];
    wf[i] = __float2half_rn(w);
}

// ---------------------------------------------------------------------------
// CSR build: histogram -> 2-level exclusive scan -> counting sort of src ids
// ---------------------------------------------------------------------------
__global__ void zero_cnt_kernel(int n8) {
    int i = blockIdx.x * blockDim.x + threadIdx.x;
    if (i < n8) g_cnt[i] = 0;
}

__global__ void hist_kernel(const int* __restrict__ ei,
                            const int* __restrict__ et, int e) {
    int i = blockIdx.x * blockDim.x + threadIdx.x;
    if (i >= e) return;
    atomicAdd(&g_cnt[ei[e + i] * NREL + et[i]], 1);
}

// each block scans 1024 elems (256 thr x 4); writes block-local exclusive, blocksum
__global__ void scan1_kernel(int n8) {
    __shared__ int sm[256];
    int t = threadIdx.x;
    int base = blockIdx.x * 1024 + t * 4;
    int v0 = 0, v1 = 0, v2 = 0, v3 = 0;
    if (base + 0 < n8) v0 = g_cnt[base + 0];
    if (base + 1 < n8) v1 = g_cnt[base + 1];
    if (base + 2 < n8) v2 = g_cnt[base + 2];
    if (base + 3 < n8) v3 = g_cnt[base + 3];
    int tsum = v0 + v1 + v2 + v3;
    sm[t] = tsum;
    __syncthreads();
#pragma unroll
    for (int d = 1; d < 256; d <<= 1) {
        int x = (t >= d) ? sm[t - d] : 0;
        __syncthreads();
        sm[t] += x;
        __syncthreads();
    }
    int run = sm[t] - tsum;   // exclusive prefix of this thread
    if (base + 0 < n8) { g_off[base + 0] = run; run += v0; }
    if (base + 1 < n8) { g_off[base + 1] = run; run += v1; }
    if (base + 2 < n8) { g_off[base + 2] = run; run += v2; }
    if (base + 3 < n8) { g_off[base + 3] = run; }
    if (t == 255) g_bsum[blockIdx.x] = sm[255];
}

__global__ void scan2_kernel(int nb) {
    __shared__ int sm[1024];
    int t = threadIdx.x;
    int v = (t < nb) ? g_bsum[t] : 0;
    sm[t] = v;
    __syncthreads();
#pragma unroll
    for (int d = 1; d < 1024; d <<= 1) {
        int x = (t >= d) ? sm[t - d] : 0;
        __syncthreads();
        sm[t] += x;
        __syncthreads();
    }
    if (t < nb) g_bsum[t] = sm[t] - v;   // exclusive
}

__global__ void scan3_kernel(int n8, int e) {
    int i = blockIdx.x * blockDim.x + threadIdx.x;
    if (i < n8) {
        int v = g_off[i] + g_bsum[i >> 10];
        g_off[i] = v;
        g_cursor[i] = v;
    }
    if (i == 0) g_off[n8] = e;
}

__global__ void sort_edges_kernel(const int* __restrict__ ei,
                                  const int* __restrict__ et, int e) {
    int i = blockIdx.x * blockDim.x + threadIdx.x;
    if (i >= e) return;
    int bin = ei[e + i] * NREL + et[i];
    int pos = atomicAdd(&g_cursor[bin], 1);
    g_esrc[pos] = ei[i];
}

// ---------------------------------------------------------------------------
// Tensor-core GEMM (mma m16n8k16 fp16, fp32 accum), ldmatrix fragments.
//   Tile: M=128 x N=128 x K=128 one-shot. 256 threads = 8 warps (4 wm x 2 wn).
//   blockIdx.x = bn (0 root->fp32 out + bias; 1..8 -> g_Yh fp16).
// ---------------------------------------------------------------------------
#define MMA16816(d, a, b)                                                  \
    asm volatile(                                                          \
        "mma.sync.aligned.m16n8k16.row.col.f32.f16.f16.f32 "               \
        "{%0,%1,%2,%3},{%4,%5,%6,%7},{%8,%9},{%0,%1,%2,%3};"               \
        : "+f"(d[0]), "+f"(d[1]), "+f"(d[2]), "+f"(d[3])                   \
        : "r"(a[0]), "r"(a[1]), "r"(a[2]), "r"(a[3]), "r"(b[0]), "r"(b[1]))

#define LDSM4(R, ADDR)                                                     \
    asm volatile("ldmatrix.sync.aligned.m8n8.x4.shared.b16 "               \
                 "{%0,%1,%2,%3}, [%4];"                                    \
                 : "=r"(R[0]), "=r"(R[1]), "=r"(R[2]), "=r"(R[3])          \
                 : "r"(ADDR))

__global__ __launch_bounds__(256) void gemm_mma_kernel(
    const __half* __restrict__ wf,   // layer base [9][128][128] (n,k)
    const float* __restrict__ bias,
    float* __restrict__ outroot, int nrows)
{
    extern __shared__ __half smem[];
    __half* sA = smem;                 // 128 x AS
    __half* sB = sA + 128 * AS;        // 128 x AS

    const int bn   = blockIdx.x;
    const int row0 = blockIdx.y * 128;
    const int tid  = threadIdx.x;
    const int lane = tid & 31;
    const int warp = tid >> 5;
    const int wm   = warp & 3;
    const int wn   = warp >> 2;
    const int grp  = lane >> 2;
    const int tg   = lane & 3;

#pragma unroll
    for (int it = 0; it < 8; it++) {
        int id = tid + it * 256;
        int r  = id >> 4;
        int c  = id & 15;
        int gr = row0 + r;
        uint4 v = make_uint4(0, 0, 0, 0);
        if (gr < nrows)
            v = *(const uint4*)(g_Af + (size_t)gr * DIM + c * 8);
        *(uint4*)(sA + r * AS + c * 8) = v;
    }
    const __half* B = wf + (size_t)bn * DIM * DIM;
#pragma unroll
    for (int it = 0; it < 8; it++) {
        int id = tid + it * 256;
        int r  = id >> 4;
        int c  = id & 15;
        *(uint4*)(sB + r * AS + c * 8) = *(const uint4*)(B + r * DIM + c * 8);
    }
    __syncthreads();

    const unsigned sAB = (unsigned)__cvta_generic_to_shared(sA);
    const unsigned sBB = (unsigned)__cvta_generic_to_shared(sB);
    const unsigned aoff = (unsigned)(((wm * 32 + (lane & 15)) * AS +
                                      ((lane >> 4) << 3)) * 2);
    const unsigned boff = (unsigned)(((wn * 64 + ((lane >> 4) << 3) + (lane & 7)) * AS +
                                      (((lane >> 3) & 1) << 3)) * 2);

    float acc[2][8][4];
#pragma unroll
    for (int mi = 0; mi < 2; mi++)
#pragma unroll
        for (int ni = 0; ni < 8; ni++)
#pragma unroll
            for (int q = 0; q < 4; q++) acc[mi][ni][q] = 0.0f;

#pragma unroll
    for (int ks = 0; ks < 8; ks++) {
        const unsigned kb = ks * 32;
        unsigned a[2][4];
#pragma unroll
        for (int mi = 0; mi < 2; mi++)
            LDSM4(a[mi], sAB + aoff + mi * (16 * AS * 2) + kb);
        unsigned b[8][2];
#pragma unroll
        for (int p = 0; p < 4; p++) {
            unsigned t[4];
            LDSM4(t, sBB + boff + p * (16 * AS * 2) + kb);
            b[2 * p][0] = t[0]; b[2 * p][1] = t[1];
            b[2 * p + 1][0] = t[2]; b[2 * p + 1][1] = t[3];
        }
#pragma unroll
        for (int ni = 0; ni < 8; ni++)
#pragma unroll
            for (int mi = 0; mi < 2; mi++)
                MMA16816(acc[mi][ni], a[mi], b[ni]);
    }

#pragma unroll
    for (int mi = 0; mi < 2; mi++) {
        int r0 = row0 + wm * 32 + mi * 16 + grp;
#pragma unroll
        for (int ni = 0; ni < 8; ni++) {
            int col = wn * 64 + ni * 8 + 2 * tg;
            if (bn == 0) {
                float b0 = bias[col], b1 = bias[col + 1];
                if (r0 < nrows) {
                    float2 o = make_float2(acc[mi][ni][0] + b0, acc[mi][ni][1] + b1);
                    *(float2*)&outroot[(size_t)r0 * DIM + col] = o;
                }
                if (r0 + 8 < nrows) {
                    float2 o = make_float2(acc[mi][ni][2] + b0, acc[mi][ni][3] + b1);
                    *(float2*)&outroot[(size_t)(r0 + 8) * DIM + col] = o;
                }
            } else {
                int rel = bn - 1;
                if (r0 < nrows) {
                    __half2 o = __floats2half2_rn(acc[mi][ni][0], acc[mi][ni][1]);
                    *(__half2*)&g_Yh[((size_t)r0 * NREL + rel) * DIM + col] = o;
                }
                if (r0 + 8 < nrows) {
                    __half2 o = __floats2half2_rn(acc[mi][ni][2], acc[mi][ni][3]);
                    *(__half2*)&g_Yh[((size_t)(r0 + 8) * NREL + rel) * DIM + col] = o;
                }
            }
        }
    }
}

// ---------------------------------------------------------------------------
// Owner-computes aggregation: one warp per dst node, no atomics.
// Two half-warps process two edges/iter; 16 lanes x LDG.128 per 256B Y row.
//   out[dst] += sum_r (1/cnt_r) * sum_{edges in bin(dst,r)} Yh[src][r]
// ---------------------------------------------------------------------------
__global__ __launch_bounds__(256) void agg_kernel(float* __restrict__ out, int n)
{
    int gw   = (blockIdx.x * 256 + threadIdx.x) >> 5;
    int lane = threadIdx.x & 31;
    if (gw >= n) return;
    const int dst  = gw;
    const int half = lane >> 4;      // which edge of the pair
    const int hl   = lane & 15;      // col group: cols hl*8 .. hl*8+7

    // segment offsets via one lane-distributed load + shfl
    int ov = 0;
    if (lane < 9) ov = g_off[dst * NREL + lane];

    float tot[8];
#pragma unroll
    for (int j = 0; j < 8; j++) tot[j] = 0.0f;

#pragma unroll
    for (int r = 0; r < NREL; r++) {
        int s0 = __shfl_sync(0xffffffffu, ov, r);
        int s1 = __shfl_sync(0xffffffffu, ov, r + 1);
        int c  = s1 - s0;
        if (c <= 0) continue;
        float acc[8];
#pragma unroll
        for (int j = 0; j < 8; j++) acc[j] = 0.0f;
        for (int i = s0 + half; i < s1; i += 2) {
            int src = g_esrc[i];
            const uint4 v = *(const uint4*)(g_Yh +
                (((size_t)src * NREL + r) << 7) + hl * 8);
            const __half2* h2 = reinterpret_cast<const __half2*>(&v);
#pragma unroll
            for (int j = 0; j < 4; j++) {
                float2 f = __half22float2(h2[j]);
                acc[2 * j]     += f.x;
                acc[2 * j + 1] += f.y;
            }
        }
        float s = 1.0f / (float)c;
#pragma unroll
        for (int j = 0; j < 8; j++) tot[j] += acc[j] * s;
    }

    // combine the two half-warps (same cols, different edges)
#pragma unroll
    for (int j = 0; j < 8; j++)
        tot[j] += __shfl_xor_sync(0xffffffffu, tot[j], 16);

    if (half == 0) {
        float4* o = (float4*)(out + (size_t)dst * DIM + hl * 8);
        float4 a = o[0], b = o[1];
        a.x += tot[0]; a.y += tot[1]; a.z += tot[2]; a.w += tot[3];
        b.x += tot[4]; b.y += tot[5]; b.z += tot[6]; b.w += tot[7];
        o[0] = a; o[1] = b;
    }
}

__global__ void relu_kernel(float* __restrict__ p, int n) {
    int i = blockIdx.x * blockDim.x + threadIdx.x;
    if (i < n) p[i] = fmaxf(p[i], 0.0f);
}

// ---------------------------------------------------------------------------
// Launch  (gemm #1 at 0-based launch index 3 — the slot ncu samples)
// ---------------------------------------------------------------------------
extern "C" void kernel_launch(void* const* d_in, const int* in_sizes, int n_in,
                              void* d_out, int out_size)
{
    const float* x   = (const float*)d_in[0];
    const int*   ei  = (const int*)d_in[1];  // [2,E] int32
    const int*   et  = (const int*)d_in[2];  // [E]   int32
    const float* rw1 = (const float*)d_in[3];
    const float* ro1 = (const float*)d_in[4];
    const float* b1  = (const float*)d_in[5];
    const float* rw2 = (const float*)d_in[6];
    const float* ro2 = (const float*)d_in[7];
    const float* b2  = (const float*)d_in[8];
    float* out = (float*)d_out;

    const int n = in_sizes[0] / DIM;
    const int e = in_sizes[2];

    float* hptr;
    cudaGetSymbolAddress((void**)&hptr, g_h);
    __half* wf;
    cudaGetSymbolAddress((void**)&wf, g_Wf);

    const int smem_bytes = 2 * 128 * AS * 2;   // 69632
    static bool attr_done = false;
    if (!attr_done) {
        cudaFuncSetAttribute(gemm_mma_kernel,
                             cudaFuncAttributeMaxDynamicSharedMemorySize, smem_bytes);
        attr_done = true;
    }

    const int n8 = n * NREL;
    const int nscan = (n8 + 1023) / 1024;      // 782 blocks
    dim3 ggrid(NREL + 1, (n + 127) / 128);
    const int nw = 9 * DIM * DIM;

    // idx 0-2: conversions
    wconvert_kernel<<<(nw + 255) / 256, 256>>>(ro1, rw1, wf);
    wconvert_kernel<<<(nw + 255) / 256, 256>>>(ro2, rw2, wf + nw);
    convert_half_kernel<<<(n * 32 + 255) / 256, 256>>>(x, n * 32, 0);

    // idx 3: layer-1 GEMM (profiled slot)
    gemm_mma_kernel<<<ggrid, 256, smem_bytes>>>(wf, b1, hptr, n);

    // idx 4-9: CSR build (shared by both layers)
    zero_cnt_kernel<<<(n8 + 255) / 256, 256>>>(n8);
    hist_kernel<<<(e + 255) / 256, 256>>>(ei, et, e);
    scan1_kernel<<<nscan, 256>>>(n8);
    scan2_kernel<<<1, 1024>>>(nscan);
    scan3_kernel<<<(n8 + 255) / 256, 256>>>(n8, e);
    sort_edges_kernel<<<(e + 255) / 256, 256>>>(ei, et, e);

    // layer 1 rest
    agg_kernel<<<(n * 32 + 255) / 256, 256>>>(hptr, n);
    convert_half_kernel<<<(n * 32 + 255) / 256, 256>>>(hptr, n * 32, 1);  // relu fused

    // layer 2
    gemm_mma_kernel<<<ggrid, 256, smem_bytes>>>(wf + nw, b2, out, n);
    agg_kernel<<<(n * 32 + 255) / 256, 256>>>(out, n);
    relu_kernel<<<(n * DIM + 255) / 256, 256>>>(out, n * DIM);
}